// round 3
// baseline (speedup 1.0000x reference)
#include <cuda_runtime.h>
#include <math.h>

#define TT 2048
#define CC 1024
#define HH 16
#define DD 64
#define EE 8
#define FF 4096

// ---------------- scratch (static device globals; no allocation) ----------------
__device__ float g_xn [TT*CC];
__device__ float g_xn2[TT*CC];
__device__ float g_att[TT*CC];
__device__ float g_q[HH*TT*DD];
__device__ float g_k[HH*TT*DD];
__device__ float g_v[HH*TT*DD];
__device__ float g_gate[TT*EE];
__device__ int   g_list [EE*TT];
__device__ float g_lgate[EE*TT];
__device__ int   g_count[EE];
__device__ float g_h[TT*FF];          // per-expert hidden, reused across experts

// ---------------- LayerNorm ----------------
// which==0 -> write g_xn, which==1 -> write g_xn2
__global__ void ln_kernel(const float* __restrict__ x, const float* __restrict__ gw,
                          const float* __restrict__ bw, int which) {
    int t = blockIdx.x;
    int tid = threadIdx.x;
    const float* row = x + (size_t)t * CC;
    float vals[4];
    float s = 0.f, s2 = 0.f;
#pragma unroll
    for (int i = 0; i < 4; i++) {
        float v = row[tid + i * 256];
        vals[i] = v; s += v; s2 += v * v;
    }
#pragma unroll
    for (int o = 16; o > 0; o >>= 1) {
        s  += __shfl_xor_sync(0xffffffffu, s, o);
        s2 += __shfl_xor_sync(0xffffffffu, s2, o);
    }
    __shared__ float red[2][8];
    __shared__ float smean, srstd;
    if ((tid & 31) == 0) { red[0][tid >> 5] = s; red[1][tid >> 5] = s2; }
    __syncthreads();
    if (tid < 32) {
        float a  = (tid < 8) ? red[0][tid] : 0.f;
        float a2 = (tid < 8) ? red[1][tid] : 0.f;
#pragma unroll
        for (int o = 4; o > 0; o >>= 1) {
            a  += __shfl_xor_sync(0xffffffffu, a, o);
            a2 += __shfl_xor_sync(0xffffffffu, a2, o);
        }
        if (tid == 0) {
            float m = a * (1.f / CC);
            smean = m;
            srstd = rsqrtf(a2 * (1.f / CC) - m * m + 1e-5f);
        }
    }
    __syncthreads();
    float m = smean, r = srstd;
    float* orow = (which == 0 ? g_xn : g_xn2) + (size_t)t * CC;
#pragma unroll
    for (int i = 0; i < 4; i++) {
        int c = tid + i * 256;
        orow[c] = (vals[i] - m) * r * gw[c] + bw[c];
    }
}

// ---------------- QKV GEMM: out[h][t][d] = sum_c xn[t][c] * W[h][c][d] ----------------
// which: 0->g_q, 1->g_k, 2->g_v. grid (1, 32, 16), block 256
__global__ void qkv_gemm(const float* __restrict__ W, int which) {
    int h = blockIdx.z;
    const float* A = g_xn;
    const float* B = W + (size_t)h * CC * DD;
    float* O = (which == 0 ? g_q : which == 1 ? g_k : g_v) + (size_t)h * TT * DD;
    int m0 = blockIdx.y * 64;
    __shared__ float As[16][64];
    __shared__ float Bs[16][64];
    int tid = threadIdx.x;
    int ty = tid >> 4, tx = tid & 15;
    int arow = tid >> 2, aq = tid & 3;
    int brow = tid >> 4, bq = tid & 15;
    float acc[4][4] = {};
    for (int k0 = 0; k0 < CC; k0 += 16) {
        float4 a = *(const float4*)(A + (size_t)(m0 + arow) * CC + k0 + aq * 4);
        float4 b = *(const float4*)(B + (size_t)(k0 + brow) * DD + bq * 4);
        __syncthreads();
        As[aq*4+0][arow] = a.x; As[aq*4+1][arow] = a.y;
        As[aq*4+2][arow] = a.z; As[aq*4+3][arow] = a.w;
        *(float4*)&Bs[brow][bq*4] = b;
        __syncthreads();
#pragma unroll
        for (int kk = 0; kk < 16; kk++) {
            float4 av = *(float4*)&As[kk][ty*4];
            float4 bv = *(float4*)&Bs[kk][tx*4];
            float a_[4] = {av.x, av.y, av.z, av.w};
            float b_[4] = {bv.x, bv.y, bv.z, bv.w};
#pragma unroll
            for (int i = 0; i < 4; i++)
#pragma unroll
                for (int j = 0; j < 4; j++) acc[i][j] += a_[i] * b_[j];
        }
    }
#pragma unroll
    for (int i = 0; i < 4; i++) {
        float4 r4 = make_float4(acc[i][0], acc[i][1], acc[i][2], acc[i][3]);
        *(float4*)(O + (size_t)(m0 + ty*4 + i) * DD + tx * 4) = r4;
    }
}

// ---------------- Flash attention (causal, online softmax) ----------------
// grid (32, 16), block 256 (16x16 threads, each owns 4x4 of S and of O)
__global__ void attn_kernel() {
    int h  = blockIdx.y;
    int m0 = blockIdx.x * 64;
    const float* Q = g_q + (size_t)h * TT * DD;
    const float* K = g_k + (size_t)h * TT * DD;
    const float* V = g_v + (size_t)h * TT * DD;
    __shared__ float Qts[64][64];   // [d][row], pre-scaled by C^-0.5
    __shared__ float KPs[64][64];   // K^T [d][col], then reused as P [row][col]
    __shared__ float Vs [64][64];   // [col][d]
    int tid = threadIdx.x, ty = tid >> 4, tx = tid & 15;
    int lr = tid >> 2, lq = tid & 3;

#pragma unroll
    for (int p = 0; p < 4; p++) {
        int d4 = lq + p * 4;
        float4 a = *(const float4*)(Q + (size_t)(m0 + lr) * DD + d4 * 4);
        const float sc = 0.03125f;  // 1/sqrt(1024)
        Qts[d4*4+0][lr] = a.x*sc; Qts[d4*4+1][lr] = a.y*sc;
        Qts[d4*4+2][lr] = a.z*sc; Qts[d4*4+3][lr] = a.w*sc;
    }

    float o[4][4] = {};
    float mrow[4], lrow[4];
#pragma unroll
    for (int i = 0; i < 4; i++) { mrow[i] = -INFINITY; lrow[i] = 0.f; }

    for (int st = 0; st <= (int)blockIdx.x; st++) {
        int s0 = st * 64;
        __syncthreads();
#pragma unroll
        for (int p = 0; p < 4; p++) {
            int d4 = lq + p * 4;
            float4 a = *(const float4*)(K + (size_t)(s0 + lr) * DD + d4 * 4);
            KPs[d4*4+0][lr] = a.x; KPs[d4*4+1][lr] = a.y;
            KPs[d4*4+2][lr] = a.z; KPs[d4*4+3][lr] = a.w;
            float4 b = *(const float4*)(V + (size_t)(s0 + lr) * DD + d4 * 4);
            *(float4*)&Vs[lr][d4*4] = b;
        }
        __syncthreads();

        float s_acc[4][4] = {};
#pragma unroll 16
        for (int d = 0; d < 64; d++) {
            float4 qv = *(float4*)&Qts[d][ty*4];
            float4 kv = *(float4*)&KPs[d][tx*4];
            float a_[4] = {qv.x, qv.y, qv.z, qv.w};
            float b_[4] = {kv.x, kv.y, kv.z, kv.w};
#pragma unroll
            for (int i = 0; i < 4; i++)
#pragma unroll
                for (int j = 0; j < 4; j++) s_acc[i][j] += a_[i] * b_[j];
        }

        bool diag = (st == (int)blockIdx.x);
#pragma unroll
        for (int i = 0; i < 4; i++) {
            int qi = m0 + ty*4 + i;
            float rmax = -INFINITY;
#pragma unroll
            for (int j = 0; j < 4; j++) {
                if (diag && (s0 + tx*4 + j) > qi) s_acc[i][j] = -INFINITY;
                rmax = fmaxf(rmax, s_acc[i][j]);
            }
#pragma unroll
            for (int off = 1; off < 16; off <<= 1)
                rmax = fmaxf(rmax, __shfl_xor_sync(0xffffffffu, rmax, off));
            float mnew = fmaxf(mrow[i], rmax);
            float corr = __expf(mrow[i] - mnew);
            float rsum = 0.f;
#pragma unroll
            for (int j = 0; j < 4; j++) {
                float p = __expf(s_acc[i][j] - mnew);
                s_acc[i][j] = p; rsum += p;
            }
#pragma unroll
            for (int off = 1; off < 16; off <<= 1)
                rsum += __shfl_xor_sync(0xffffffffu, rsum, off);
            lrow[i] = lrow[i] * corr + rsum;
            mrow[i] = mnew;
#pragma unroll
            for (int j = 0; j < 4; j++) o[i][j] *= corr;
        }
        __syncthreads();            // all S reads of KPs done
#pragma unroll
        for (int i = 0; i < 4; i++)
            *(float4*)&KPs[ty*4+i][tx*4] =
                make_float4(s_acc[i][0], s_acc[i][1], s_acc[i][2], s_acc[i][3]);
        __syncthreads();

#pragma unroll 16
        for (int j = 0; j < 64; j++) {
            float4 vv = *(float4*)&Vs[j][tx*4];
            float p0 = KPs[ty*4+0][j], p1 = KPs[ty*4+1][j];
            float p2 = KPs[ty*4+2][j], p3 = KPs[ty*4+3][j];
            o[0][0]+=p0*vv.x; o[0][1]+=p0*vv.y; o[0][2]+=p0*vv.z; o[0][3]+=p0*vv.w;
            o[1][0]+=p1*vv.x; o[1][1]+=p1*vv.y; o[1][2]+=p1*vv.z; o[1][3]+=p1*vv.w;
            o[2][0]+=p2*vv.x; o[2][1]+=p2*vv.y; o[2][2]+=p2*vv.z; o[2][3]+=p2*vv.w;
            o[3][0]+=p3*vv.x; o[3][1]+=p3*vv.y; o[3][2]+=p3*vv.z; o[3][3]+=p3*vv.w;
        }
    }
#pragma unroll
    for (int i = 0; i < 4; i++) {
        float inv = 1.f / lrow[i];
        float4 r4 = make_float4(o[i][0]*inv, o[i][1]*inv, o[i][2]*inv, o[i][3]*inv);
        *(float4*)(g_att + (size_t)(m0 + ty*4 + i) * CC + h * DD + tx * 4) = r4;
    }
}

// ---------------- proj GEMM + bias + residual: out = x + att@Wp + bp ----------------
// grid (16, 32)
__global__ void proj_gemm(const float* __restrict__ W, const float* __restrict__ bias,
                          const float* __restrict__ xres, float* __restrict__ out) {
    int m0 = blockIdx.y * 64, n0 = blockIdx.x * 64;
    __shared__ float As[16][64];
    __shared__ float Bs[16][64];
    int tid = threadIdx.x;
    int ty = tid >> 4, tx = tid & 15;
    int arow = tid >> 2, aq = tid & 3;
    int brow = tid >> 4, bq = tid & 15;
    float acc[4][4] = {};
    for (int k0 = 0; k0 < CC; k0 += 16) {
        float4 a = *(const float4*)(g_att + (size_t)(m0 + arow) * CC + k0 + aq * 4);
        float4 b = *(const float4*)(W + (size_t)(k0 + brow) * CC + n0 + bq * 4);
        __syncthreads();
        As[aq*4+0][arow] = a.x; As[aq*4+1][arow] = a.y;
        As[aq*4+2][arow] = a.z; As[aq*4+3][arow] = a.w;
        *(float4*)&Bs[brow][bq*4] = b;
        __syncthreads();
#pragma unroll
        for (int kk = 0; kk < 16; kk++) {
            float4 av = *(float4*)&As[kk][ty*4];
            float4 bv = *(float4*)&Bs[kk][tx*4];
            float a_[4] = {av.x, av.y, av.z, av.w};
            float b_[4] = {bv.x, bv.y, bv.z, bv.w};
#pragma unroll
            for (int i = 0; i < 4; i++)
#pragma unroll
                for (int j = 0; j < 4; j++) acc[i][j] += a_[i] * b_[j];
        }
    }
    float4 bb = *(const float4*)(bias + n0 + tx * 4);
#pragma unroll
    for (int i = 0; i < 4; i++) {
        size_t idx = (size_t)(m0 + ty*4 + i) * CC + n0 + tx * 4;
        float4 xr = *(const float4*)(xres + idx);
        float4 r4 = make_float4(xr.x + acc[i][0] + bb.x, xr.y + acc[i][1] + bb.y,
                                xr.z + acc[i][2] + bb.z, xr.w + acc[i][3] + bb.w);
        *(float4*)(out + idx) = r4;
    }
}

// ---------------- router: noisy top-2 gate ----------------
// grid 2048, block 256 (8 warps = 8 experts)
__global__ void router_kernel(const float* __restrict__ Wr, const float* __restrict__ br,
                              const float* __restrict__ Wn, const float* __restrict__ bn,
                              const float* __restrict__ noise) {
    int t = blockIdx.x;
    int tid = threadIdx.x, e = tid >> 5, lane = tid & 31;
    const float* xr = g_xn2 + (size_t)t * CC;
    float sl = 0.f, sn = 0.f;
    for (int c = lane; c < CC; c += 32) {
        float xv = xr[c];
        sl += xv * Wr[c * EE + e];
        sn += xv * Wn[c * EE + e];
    }
#pragma unroll
    for (int o = 16; o > 0; o >>= 1) {
        sl += __shfl_xor_sync(0xffffffffu, sl, o);
        sn += __shfl_xor_sync(0xffffffffu, sn, o);
    }
    __shared__ float s_noisy[EE];
    if (lane == 0) {
        float lg = sl + br[e];
        float nl = sn + bn[e];
        float sp = (nl > 20.f) ? nl : log1pf(expf(nl));
        s_noisy[e] = lg + noise[(size_t)t * EE + e] * sp;
    }
    __syncthreads();
    if (tid == 0) {
        float n[EE];
#pragma unroll
        for (int i = 0; i < EE; i++) n[i] = s_noisy[i];
        int i1 = 0;
        for (int i = 1; i < EE; i++) if (n[i] > n[i1]) i1 = i;
        int i2 = -1;
        for (int i = 0; i < EE; i++) {
            if (i == i1) continue;
            if (i2 < 0 || n[i] > n[i2]) i2 = i;
        }
        float mx = fmaxf(n[i1], n[i2]);
        float e1 = __expf(n[i1] - mx), e2 = __expf(n[i2] - mx);
        float inv = 1.f / (e1 + e2);
#pragma unroll
        for (int i = 0; i < EE; i++) g_gate[(size_t)t * EE + i] = 0.f;
        g_gate[(size_t)t * EE + i1] = e1 * inv;
        g_gate[(size_t)t * EE + i2] = e2 * inv;
    }
}

// ---------------- deterministic per-expert token lists ----------------
__global__ void build_lists() {
    int e = threadIdx.x >> 5, lane = threadIdx.x & 31;
    int cnt = 0;
    for (int base = 0; base < TT; base += 32) {
        int t = base + lane;
        float gv = g_gate[(size_t)t * EE + e];
        unsigned mask = __ballot_sync(0xffffffffu, gv > 0.f);
        if (gv > 0.f) {
            int pos = cnt + __popc(mask & ((1u << lane) - 1u));
            g_list [e * TT + pos] = t;
            g_lgate[e * TT + pos] = gv;
        }
        cnt += __popc(mask);
    }
    if (lane == 0) g_count[e] = cnt;
}

// ---------------- MoE layer 1: h = relu(xn2[list]@W1[e] + b1[e]) ----------------
// grid (64, 32)
__global__ void moe_gemm1(const float* __restrict__ W1, const float* __restrict__ b1, int e) {
    int Ne = g_count[e];
    int m0 = blockIdx.y * 64;
    if (m0 >= Ne) return;
    int n0 = blockIdx.x * 64;
    const float* B = W1 + (size_t)e * CC * FF;
    const float* bias = b1 + (size_t)e * FF;
    __shared__ float As[16][64];
    __shared__ float Bs[16][64];
    __shared__ int rows[64];
    int tid = threadIdx.x;
    int ty = tid >> 4, tx = tid & 15;
    int arow = tid >> 2, aq = tid & 3;
    int brow = tid >> 4, bq = tid & 15;
    if (tid < 64) rows[tid] = (m0 + tid < Ne) ? g_list[e * TT + m0 + tid] : 0;
    __syncthreads();
    int ar = rows[arow];
    float acc[4][4] = {};
    for (int k0 = 0; k0 < CC; k0 += 16) {
        float4 a = *(const float4*)(g_xn2 + (size_t)ar * CC + k0 + aq * 4);
        float4 b = *(const float4*)(B + (size_t)(k0 + brow) * FF + n0 + bq * 4);
        __syncthreads();
        As[aq*4+0][arow] = a.x; As[aq*4+1][arow] = a.y;
        As[aq*4+2][arow] = a.z; As[aq*4+3][arow] = a.w;
        *(float4*)&Bs[brow][bq*4] = b;
        __syncthreads();
#pragma unroll
        for (int kk = 0; kk < 16; kk++) {
            float4 av = *(float4*)&As[kk][ty*4];
            float4 bv = *(float4*)&Bs[kk][tx*4];
            float a_[4] = {av.x, av.y, av.z, av.w};
            float b_[4] = {bv.x, bv.y, bv.z, bv.w};
#pragma unroll
            for (int i = 0; i < 4; i++)
#pragma unroll
                for (int j = 0; j < 4; j++) acc[i][j] += a_[i] * b_[j];
        }
    }
    float4 bb = *(const float4*)(bias + n0 + tx * 4);
#pragma unroll
    for (int i = 0; i < 4; i++) {
        int m = m0 + ty*4 + i;
        if (m < Ne) {
            float4 r4 = make_float4(fmaxf(acc[i][0] + bb.x, 0.f),
                                    fmaxf(acc[i][1] + bb.y, 0.f),
                                    fmaxf(acc[i][2] + bb.z, 0.f),
                                    fmaxf(acc[i][3] + bb.w, 0.f));
            *(float4*)(g_h + (size_t)m * FF + n0 + tx * 4) = r4;
        }
    }
}

// ---------------- MoE layer 2: out[tok] += gate * (h@W2[e] + b2[e]) ----------------
// grid (16, 32)
__global__ void moe_gemm2(const float* __restrict__ W2, const float* __restrict__ b2,
                          float* __restrict__ out, int e) {
    int Ne = g_count[e];
    int m0 = blockIdx.y * 64;
    if (m0 >= Ne) return;
    int n0 = blockIdx.x * 64;
    const float* B = W2 + (size_t)e * FF * CC;
    const float* bias = b2 + (size_t)e * CC;
    __shared__ float As[16][64];
    __shared__ float Bs[16][64];
    int tid = threadIdx.x;
    int ty = tid >> 4, tx = tid & 15;
    int arow = tid >> 2, aq = tid & 3;
    int brow = tid >> 4, bq = tid & 15;
    float acc[4][4] = {};
    for (int k0 = 0; k0 < FF; k0 += 16) {
        float4 a = *(const float4*)(g_h + (size_t)(m0 + arow) * FF + k0 + aq * 4);
        float4 b = *(const float4*)(B + (size_t)(k0 + brow) * CC + n0 + bq * 4);
        __syncthreads();
        As[aq*4+0][arow] = a.x; As[aq*4+1][arow] = a.y;
        As[aq*4+2][arow] = a.z; As[aq*4+3][arow] = a.w;
        *(float4*)&Bs[brow][bq*4] = b;
        __syncthreads();
#pragma unroll
        for (int kk = 0; kk < 16; kk++) {
            float4 av = *(float4*)&As[kk][ty*4];
            float4 bv = *(float4*)&Bs[kk][tx*4];
            float a_[4] = {av.x, av.y, av.z, av.w};
            float b_[4] = {bv.x, bv.y, bv.z, bv.w};
#pragma unroll
            for (int i = 0; i < 4; i++)
#pragma unroll
                for (int j = 0; j < 4; j++) acc[i][j] += a_[i] * b_[j];
        }
    }
    float4 bb = *(const float4*)(bias + n0 + tx * 4);
#pragma unroll
    for (int i = 0; i < 4; i++) {
        int m = m0 + ty*4 + i;
        if (m < Ne) {
            int tok = g_list[e * TT + m];
            float gv = g_lgate[e * TT + m];
            float4* op = (float4*)(out + (size_t)tok * CC + n0 + tx * 4);
            float4 o4 = *op;
            o4.x += gv * (acc[i][0] + bb.x);
            o4.y += gv * (acc[i][1] + bb.y);
            o4.z += gv * (acc[i][2] + bb.z);
            o4.w += gv * (acc[i][3] + bb.w);
            *op = o4;
        }
    }
}

// ---------------- host launcher ----------------
extern "C" void kernel_launch(void* const* d_in, const int* in_sizes, int n_in,
                              void* d_out, int out_size) {
    const float* x     = (const float*)d_in[0];
    const float* noise = (const float*)d_in[1];
    const float* ln1_g = (const float*)d_in[2];
    const float* ln1_b = (const float*)d_in[3];
    const float* ln2_g = (const float*)d_in[4];
    const float* ln2_b = (const float*)d_in[5];
    const float* Wq    = (const float*)d_in[6];
    const float* Wk    = (const float*)d_in[7];
    const float* Wv    = (const float*)d_in[8];
    const float* Wp    = (const float*)d_in[9];
    const float* bp    = (const float*)d_in[10];
    const float* Wr    = (const float*)d_in[11];
    const float* br    = (const float*)d_in[12];
    const float* Wn    = (const float*)d_in[13];
    const float* bn    = (const float*)d_in[14];
    const float* W1    = (const float*)d_in[15];
    const float* b1    = (const float*)d_in[16];
    const float* W2    = (const float*)d_in[17];
    const float* b2    = (const float*)d_in[18];
    float* out = (float*)d_out;

    // LN1
    ln_kernel<<<TT, 256>>>(x, ln1_g, ln1_b, 0);
    // QKV
    dim3 gq(1, TT / 64, HH);
    qkv_gemm<<<gq, 256>>>(Wq, 0);
    qkv_gemm<<<gq, 256>>>(Wk, 1);
    qkv_gemm<<<gq, 256>>>(Wv, 2);
    // attention
    attn_kernel<<<dim3(TT / 64, HH), 256>>>();
    // proj + residual -> out (= x1)
    proj_gemm<<<dim3(CC / 64, TT / 64), 256>>>(Wp, bp, x, out);
    // LN2 on x1
    ln_kernel<<<TT, 256>>>(out, ln2_g, ln2_b, 1);
    // router + lists
    router_kernel<<<TT, 256>>>(Wr, br, Wn, bn, noise);
    build_lists<<<1, 256>>>();
    // MoE experts, sequential (deterministic accumulation into out)
    for (int e = 0; e < EE; e++) {
        moe_gemm1<<<dim3(FF / 64, TT / 64), 256>>>(W1, b1, e);
        moe_gemm2<<<dim3(CC / 64, TT / 64), 256>>>(W2, b2, out, e);
    }
}

// round 8
// speedup vs baseline: 1.9500x; 1.9500x over previous
#include <cuda_runtime.h>
#include <math.h>

#define TT 2048
#define CC 1024
#define HH 16
#define DD 64
#define EE 8
#define FF 4096

// ---------------- scratch (static device globals; no allocation) ----------------
__device__ float g_xn [TT*CC];
__device__ float g_xn2[TT*CC];
__device__ float g_att[TT*CC];
__device__ float g_q[HH*TT*DD];
__device__ float g_k[HH*TT*DD];
__device__ float g_v[HH*TT*DD];
__device__ float g_gate[TT*EE];
__device__ int   g_list [EE*TT];
__device__ float g_lgate[EE*TT];
__device__ int   g_count[EE];
__device__ float g_h[TT*FF];

// ---------------- tf32 helpers ----------------
__device__ __forceinline__ unsigned f2tf(float f) {
    unsigned u;
    asm("cvt.rna.tf32.f32 %0, %1;" : "=r"(u) : "f"(f));
    return u;
}
__device__ __forceinline__ void cvt4(unsigned* dst, float4 v) {
    dst[0] = f2tf(v.x); dst[1] = f2tf(v.y); dst[2] = f2tf(v.z); dst[3] = f2tf(v.w);
}
// split: hi = tf32(x), lo = tf32(x - hi)
__device__ __forceinline__ void split4(unsigned* hi, unsigned* lo, float4 v) {
    float f[4] = {v.x, v.y, v.z, v.w};
#pragma unroll
    for (int i = 0; i < 4; i++) {
        unsigned h = f2tf(f[i]);
        hi[i] = h;
        float hf = __uint_as_float(h);   // tf32 values are valid fp32
        lo[i] = f2tf(f[i] - hf);
    }
}
__device__ __forceinline__ void mma_tf32(float* c, const unsigned* a, const unsigned* b) {
    asm volatile("mma.sync.aligned.m16n8k8.row.col.f32.tf32.tf32.f32 "
                 "{%0,%1,%2,%3},{%4,%5,%6,%7},{%8,%9},{%0,%1,%2,%3};"
                 : "+f"(c[0]), "+f"(c[1]), "+f"(c[2]), "+f"(c[3])
                 : "r"(a[0]), "r"(a[1]), "r"(a[2]), "r"(a[3]),
                   "r"(b[0]), "r"(b[1]));
}

#define AP 36    // As row stride, 32-K-chunk kernels
#define BP 72    // Bs row stride
#define AP2 20   // As row stride, 16-K-chunk 3x kernels

// ---- 1x tf32 chunk (K=32) ----
#define MMA_CHUNK(As, Bs, acc, wm, wn, g, t4)                                   \
    _Pragma("unroll")                                                           \
    for (int ks = 0; ks < 4; ks++) {                                            \
        int kb = ks * 8;                                                        \
        unsigned afr[2][4], bfr[4][2];                                          \
        _Pragma("unroll")                                                       \
        for (int mi = 0; mi < 2; mi++) {                                        \
            int r0 = (wm)*32 + mi*16 + (g);                                     \
            afr[mi][0] = As[r0  ][kb + (t4)];                                   \
            afr[mi][1] = As[r0+8][kb + (t4)];                                   \
            afr[mi][2] = As[r0  ][kb + 4 + (t4)];                               \
            afr[mi][3] = As[r0+8][kb + 4 + (t4)];                               \
        }                                                                       \
        _Pragma("unroll")                                                       \
        for (int ni = 0; ni < 4; ni++) {                                        \
            int c0 = (wn)*32 + ni*8 + (g);                                      \
            bfr[ni][0] = Bs[kb + (t4)    ][c0];                                 \
            bfr[ni][1] = Bs[kb + 4 + (t4)][c0];                                 \
        }                                                                       \
        _Pragma("unroll")                                                       \
        for (int mi = 0; mi < 2; mi++)                                          \
            _Pragma("unroll")                                                   \
            for (int ni = 0; ni < 4; ni++)                                      \
                mma_tf32(acc[mi][ni], afr[mi], bfr[ni]);                        \
    }

// ---- 3x tf32 chunk (K=16, hi/lo split operands) ----
#define MMA_CHUNK3(Ah, Al, Bh, Bl, acc, wm, wn, g, t4)                          \
    _Pragma("unroll")                                                           \
    for (int ks = 0; ks < 2; ks++) {                                            \
        int kb = ks * 8;                                                        \
        unsigned ah[2][4], al[2][4], bh[4][2], bl[4][2];                        \
        _Pragma("unroll")                                                       \
        for (int mi = 0; mi < 2; mi++) {                                        \
            int r0 = (wm)*32 + mi*16 + (g);                                     \
            ah[mi][0]=Ah[r0  ][kb+(t4)];   al[mi][0]=Al[r0  ][kb+(t4)];         \
            ah[mi][1]=Ah[r0+8][kb+(t4)];   al[mi][1]=Al[r0+8][kb+(t4)];         \
            ah[mi][2]=Ah[r0  ][kb+4+(t4)]; al[mi][2]=Al[r0  ][kb+4+(t4)];       \
            ah[mi][3]=Ah[r0+8][kb+4+(t4)]; al[mi][3]=Al[r0+8][kb+4+(t4)];       \
        }                                                                       \
        _Pragma("unroll")                                                       \
        for (int ni = 0; ni < 4; ni++) {                                        \
            int c0 = (wn)*32 + ni*8 + (g);                                      \
            bh[ni][0]=Bh[kb+(t4)  ][c0];   bl[ni][0]=Bl[kb+(t4)  ][c0];         \
            bh[ni][1]=Bh[kb+4+(t4)][c0];   bl[ni][1]=Bl[kb+4+(t4)][c0];         \
        }                                                                       \
        _Pragma("unroll")                                                       \
        for (int mi = 0; mi < 2; mi++)                                          \
            _Pragma("unroll")                                                   \
            for (int ni = 0; ni < 4; ni++) {                                    \
                mma_tf32(acc[mi][ni], ah[mi], bh[ni]);                          \
                mma_tf32(acc[mi][ni], ah[mi], bl[ni]);                          \
                mma_tf32(acc[mi][ni], al[mi], bh[ni]);                          \
            }                                                                   \
    }

// ---------------- LayerNorm ----------------
__global__ void ln_kernel(const float* __restrict__ x, const float* __restrict__ gw,
                          const float* __restrict__ bw, int which) {
    int t = blockIdx.x;
    int tid = threadIdx.x;
    const float* row = x + (size_t)t * CC;
    float vals[4];
    float s = 0.f, s2 = 0.f;
#pragma unroll
    for (int i = 0; i < 4; i++) {
        float v = row[tid + i * 256];
        vals[i] = v; s += v; s2 += v * v;
    }
#pragma unroll
    for (int o = 16; o > 0; o >>= 1) {
        s  += __shfl_xor_sync(0xffffffffu, s, o);
        s2 += __shfl_xor_sync(0xffffffffu, s2, o);
    }
    __shared__ float red[2][8];
    __shared__ float smean, srstd;
    if ((tid & 31) == 0) { red[0][tid >> 5] = s; red[1][tid >> 5] = s2; }
    __syncthreads();
    if (tid < 32) {
        float a  = (tid < 8) ? red[0][tid] : 0.f;
        float a2 = (tid < 8) ? red[1][tid] : 0.f;
#pragma unroll
        for (int o = 4; o > 0; o >>= 1) {
            a  += __shfl_xor_sync(0xffffffffu, a, o);
            a2 += __shfl_xor_sync(0xffffffffu, a2, o);
        }
        if (tid == 0) {
            float m = a * (1.f / CC);
            smean = m;
            srstd = rsqrtf(a2 * (1.f / CC) - m * m + 1e-5f);
        }
    }
    __syncthreads();
    float m = smean, r = srstd;
    float* orow = (which == 0 ? g_xn : g_xn2) + (size_t)t * CC;
#pragma unroll
    for (int i = 0; i < 4; i++) {
        int c = tid + i * 256;
        orow[c] = (vals[i] - m) * r * gw[c] + bw[c];
    }
}

// ---------------- QKV 3xTF32 GEMM: tile 128x64, K-chunk 16, grid (Mtiles, H) ----------------
__global__ __launch_bounds__(256, 2) void qkv_tc(const float* __restrict__ W, int which) {
    int h = blockIdx.y;
    int m0 = blockIdx.x * 128;
    const float* B = W + (size_t)h * CC * DD;
    float* O = (which == 0 ? g_q : which == 1 ? g_k : g_v) + (size_t)h * TT * DD;
    __shared__ unsigned Ah[128][AP2], Al[128][AP2];
    __shared__ unsigned Bh[16][BP],  Bl[16][BP];
    int tid = threadIdx.x, lane = tid & 31, warp = tid >> 5;
    int wm = warp >> 1, wn = warp & 1, g = lane >> 2, t4 = lane & 3;
    float acc[2][4][4] = {};
    for (int k0 = 0; k0 < CC; k0 += 16) {
        float4 av[2], bv;
#pragma unroll
        for (int i = 0; i < 2; i++) {
            int idx = tid + i * 256, r = idx >> 2, c4 = (idx & 3) * 4;
            av[i] = *(const float4*)(g_xn + (size_t)(m0 + r) * CC + k0 + c4);
        }
        {
            int r = tid >> 4, c4 = (tid & 15) * 4;
            bv = *(const float4*)(B + (size_t)(k0 + r) * DD + c4);
        }
        __syncthreads();
#pragma unroll
        for (int i = 0; i < 2; i++) {
            int idx = tid + i * 256, r = idx >> 2, c4 = (idx & 3) * 4;
            split4(&Ah[r][c4], &Al[r][c4], av[i]);
        }
        {
            int r = tid >> 4, c4 = (tid & 15) * 4;
            split4(&Bh[r][c4], &Bl[r][c4], bv);
        }
        __syncthreads();
        MMA_CHUNK3(Ah, Al, Bh, Bl, acc, wm, wn, g, t4)
    }
#pragma unroll
    for (int mi = 0; mi < 2; mi++)
#pragma unroll
        for (int ni = 0; ni < 4; ni++) {
            int row = m0 + wm*32 + mi*16 + g;
            int col = wn*32 + ni*8 + 2*t4;
            float* c = acc[mi][ni];
            *(float2*)(O + (size_t)row * DD + col)     = make_float2(c[0], c[1]);
            *(float2*)(O + (size_t)(row+8) * DD + col) = make_float2(c[2], c[3]);
        }
}

// ---------------- Flash attention (causal, online softmax, fp32 SIMT) ----------------
__global__ void attn_kernel() {
    int h  = blockIdx.y;
    int m0 = blockIdx.x * 64;
    const float* Q = g_q + (size_t)h * TT * DD;
    const float* K = g_k + (size_t)h * TT * DD;
    const float* V = g_v + (size_t)h * TT * DD;
    __shared__ float Qts[64][64];
    __shared__ float KPs[64][64];
    __shared__ float Vs [64][64];
    int tid = threadIdx.x, ty = tid >> 4, tx = tid & 15;
    int lr = tid >> 2, lq = tid & 3;

#pragma unroll
    for (int p = 0; p < 4; p++) {
        int d4 = lq + p * 4;
        float4 a = *(const float4*)(Q + (size_t)(m0 + lr) * DD + d4 * 4);
        const float sc = 0.03125f;
        Qts[d4*4+0][lr] = a.x*sc; Qts[d4*4+1][lr] = a.y*sc;
        Qts[d4*4+2][lr] = a.z*sc; Qts[d4*4+3][lr] = a.w*sc;
    }

    float o[4][4] = {};
    float mrow[4], lrow[4];
#pragma unroll
    for (int i = 0; i < 4; i++) { mrow[i] = -INFINITY; lrow[i] = 0.f; }

    for (int st = 0; st <= (int)blockIdx.x; st++) {
        int s0 = st * 64;
        __syncthreads();
#pragma unroll
        for (int p = 0; p < 4; p++) {
            int d4 = lq + p * 4;
            float4 a = *(const float4*)(K + (size_t)(s0 + lr) * DD + d4 * 4);
            KPs[d4*4+0][lr] = a.x; KPs[d4*4+1][lr] = a.y;
            KPs[d4*4+2][lr] = a.z; KPs[d4*4+3][lr] = a.w;
            float4 b = *(const float4*)(V + (size_t)(s0 + lr) * DD + d4 * 4);
            *(float4*)&Vs[lr][d4*4] = b;
        }
        __syncthreads();

        float s_acc[4][4] = {};
#pragma unroll 16
        for (int d = 0; d < 64; d++) {
            float4 qv = *(float4*)&Qts[d][ty*4];
            float4 kv = *(float4*)&KPs[d][tx*4];
            float a_[4] = {qv.x, qv.y, qv.z, qv.w};
            float b_[4] = {kv.x, kv.y, kv.z, kv.w};
#pragma unroll
            for (int i = 0; i < 4; i++)
#pragma unroll
                for (int j = 0; j < 4; j++) s_acc[i][j] += a_[i] * b_[j];
        }

        bool diag = (st == (int)blockIdx.x);
#pragma unroll
        for (int i = 0; i < 4; i++) {
            int qi = m0 + ty*4 + i;
            float rmax = -INFINITY;
#pragma unroll
            for (int j = 0; j < 4; j++) {
                if (diag && (s0 + tx*4 + j) > qi) s_acc[i][j] = -INFINITY;
                rmax = fmaxf(rmax, s_acc[i][j]);
            }
#pragma unroll
            for (int off = 1; off < 16; off <<= 1)
                rmax = fmaxf(rmax, __shfl_xor_sync(0xffffffffu, rmax, off));
            float mnew = fmaxf(mrow[i], rmax);
            float corr = __expf(mrow[i] - mnew);
            float rsum = 0.f;
#pragma unroll
            for (int j = 0; j < 4; j++) {
                float p = __expf(s_acc[i][j] - mnew);
                s_acc[i][j] = p; rsum += p;
            }
#pragma unroll
            for (int off = 1; off < 16; off <<= 1)
                rsum += __shfl_xor_sync(0xffffffffu, rsum, off);
            lrow[i] = lrow[i] * corr + rsum;
            mrow[i] = mnew;
#pragma unroll
            for (int j = 0; j < 4; j++) o[i][j] *= corr;
        }
        __syncthreads();
#pragma unroll
        for (int i = 0; i < 4; i++)
            *(float4*)&KPs[ty*4+i][tx*4] =
                make_float4(s_acc[i][0], s_acc[i][1], s_acc[i][2], s_acc[i][3]);
        __syncthreads();

#pragma unroll 16
        for (int j = 0; j < 64; j++) {
            float4 vv = *(float4*)&Vs[j][tx*4];
            float p0 = KPs[ty*4+0][j], p1 = KPs[ty*4+1][j];
            float p2 = KPs[ty*4+2][j], p3 = KPs[ty*4+3][j];
            o[0][0]+=p0*vv.x; o[0][1]+=p0*vv.y; o[0][2]+=p0*vv.z; o[0][3]+=p0*vv.w;
            o[1][0]+=p1*vv.x; o[1][1]+=p1*vv.y; o[1][2]+=p1*vv.z; o[1][3]+=p1*vv.w;
            o[2][0]+=p2*vv.x; o[2][1]+=p2*vv.y; o[2][2]+=p2*vv.z; o[2][3]+=p2*vv.w;
            o[3][0]+=p3*vv.x; o[3][1]+=p3*vv.y; o[3][2]+=p3*vv.z; o[3][3]+=p3*vv.w;
        }
    }
#pragma unroll
    for (int i = 0; i < 4; i++) {
        float inv = 1.f / lrow[i];
        float4 r4 = make_float4(o[i][0]*inv, o[i][1]*inv, o[i][2]*inv, o[i][3]*inv);
        *(float4*)(g_att + (size_t)(m0 + ty*4 + i) * CC + h * DD + tx * 4) = r4;
    }
}

// ---------------- proj 3xTF32 GEMM + bias + residual ----------------
__global__ __launch_bounds__(256, 2) void proj_tc(const float* __restrict__ W, const float* __restrict__ bias,
                         const float* __restrict__ xres, float* __restrict__ out) {
    int m0 = blockIdx.y * 128, n0 = blockIdx.x * 64;
    __shared__ unsigned Ah[128][AP2], Al[128][AP2];
    __shared__ unsigned Bh[16][BP],  Bl[16][BP];
    int tid = threadIdx.x, lane = tid & 31, warp = tid >> 5;
    int wm = warp >> 1, wn = warp & 1, g = lane >> 2, t4 = lane & 3;
    float acc[2][4][4] = {};
    for (int k0 = 0; k0 < CC; k0 += 16) {
        float4 av[2], bv;
#pragma unroll
        for (int i = 0; i < 2; i++) {
            int idx = tid + i * 256, r = idx >> 2, c4 = (idx & 3) * 4;
            av[i] = *(const float4*)(g_att + (size_t)(m0 + r) * CC + k0 + c4);
        }
        {
            int r = tid >> 4, c4 = (tid & 15) * 4;
            bv = *(const float4*)(W + (size_t)(k0 + r) * CC + n0 + c4);
        }
        __syncthreads();
#pragma unroll
        for (int i = 0; i < 2; i++) {
            int idx = tid + i * 256, r = idx >> 2, c4 = (idx & 3) * 4;
            split4(&Ah[r][c4], &Al[r][c4], av[i]);
        }
        {
            int r = tid >> 4, c4 = (tid & 15) * 4;
            split4(&Bh[r][c4], &Bl[r][c4], bv);
        }
        __syncthreads();
        MMA_CHUNK3(Ah, Al, Bh, Bl, acc, wm, wn, g, t4)
    }
#pragma unroll
    for (int mi = 0; mi < 2; mi++)
#pragma unroll
        for (int ni = 0; ni < 4; ni++) {
            int row = m0 + wm*32 + mi*16 + g;
            int col = n0 + wn*32 + ni*8 + 2*t4;
            float* c = acc[mi][ni];
            float2 bb = *(const float2*)(bias + col);
#pragma unroll
            for (int rr = 0; rr < 2; rr++) {
                size_t idx = (size_t)(row + rr*8) * CC + col;
                float2 xr = *(const float2*)(xres + idx);
                *(float2*)(out + idx) = make_float2(xr.x + c[rr*2+0] + bb.x,
                                                    xr.y + c[rr*2+1] + bb.y);
            }
        }
}

// ---------------- router: noisy top-2 gate (fp32) ----------------
__global__ void router_kernel(const float* __restrict__ Wr, const float* __restrict__ br,
                              const float* __restrict__ Wn, const float* __restrict__ bn,
                              const float* __restrict__ noise) {
    int t = blockIdx.x;
    int tid = threadIdx.x, e = tid >> 5, lane = tid & 31;
    const float* xr = g_xn2 + (size_t)t * CC;
    float sl = 0.f, sn = 0.f;
    for (int c = lane; c < CC; c += 32) {
        float xv = xr[c];
        sl += xv * Wr[c * EE + e];
        sn += xv * Wn[c * EE + e];
    }
#pragma unroll
    for (int o = 16; o > 0; o >>= 1) {
        sl += __shfl_xor_sync(0xffffffffu, sl, o);
        sn += __shfl_xor_sync(0xffffffffu, sn, o);
    }
    __shared__ float s_noisy[EE];
    if (lane == 0) {
        float lg = sl + br[e];
        float nl = sn + bn[e];
        float sp = (nl > 20.f) ? nl : log1pf(expf(nl));
        s_noisy[e] = lg + noise[(size_t)t * EE + e] * sp;
    }
    __syncthreads();
    if (tid == 0) {
        float n[EE];
#pragma unroll
        for (int i = 0; i < EE; i++) n[i] = s_noisy[i];
        int i1 = 0;
        for (int i = 1; i < EE; i++) if (n[i] > n[i1]) i1 = i;
        int i2 = -1;
        for (int i = 0; i < EE; i++) {
            if (i == i1) continue;
            if (i2 < 0 || n[i] > n[i2]) i2 = i;
        }
        float mx = fmaxf(n[i1], n[i2]);
        float e1 = __expf(n[i1] - mx), e2 = __expf(n[i2] - mx);
        float inv = 1.f / (e1 + e2);
#pragma unroll
        for (int i = 0; i < EE; i++) g_gate[(size_t)t * EE + i] = 0.f;
        g_gate[(size_t)t * EE + i1] = e1 * inv;
        g_gate[(size_t)t * EE + i2] = e2 * inv;
    }
}

// ---------------- deterministic per-expert token lists ----------------
__global__ void build_lists() {
    int e = threadIdx.x >> 5, lane = threadIdx.x & 31;
    int cnt = 0;
    for (int base = 0; base < TT; base += 32) {
        int t = base + lane;
        float gv = g_gate[(size_t)t * EE + e];
        unsigned mask = __ballot_sync(0xffffffffu, gv > 0.f);
        if (gv > 0.f) {
            int pos = cnt + __popc(mask & ((1u << lane) - 1u));
            g_list [e * TT + pos] = t;
            g_lgate[e * TT + pos] = gv;
        }
        cnt += __popc(mask);
    }
    if (lane == 0) g_count[e] = cnt;
}

// ---------------- MoE layer 1 (1xTF32, gathered A): h = relu(xn2[list]@W1[e] + b1) ----------------
__global__ __launch_bounds__(256, 2) void moe1_tc(const float* __restrict__ W1, const float* __restrict__ b1, int e) {
    int Ne = g_count[e];
    int m0 = blockIdx.y * 128;
    if (m0 >= Ne) return;
    int n0 = blockIdx.x * 64;
    const float* B = W1 + (size_t)e * CC * FF;
    const float* bias = b1 + (size_t)e * FF;
    __shared__ unsigned As[128][AP];
    __shared__ unsigned Bs[32][BP];
    __shared__ int rows[128];
    int tid = threadIdx.x, lane = tid & 31, warp = tid >> 5;
    int wm = warp >> 1, wn = warp & 1, g = lane >> 2, t4 = lane & 3;
    if (tid < 128) rows[tid] = (m0 + tid < Ne) ? g_list[e * TT + m0 + tid] : 0;
    __syncthreads();
    float acc[2][4][4] = {};
    for (int k0 = 0; k0 < CC; k0 += 32) {
        float4 av[4], bv[2];
#pragma unroll
        for (int i = 0; i < 4; i++) {
            int idx = tid + i * 256, r = idx >> 3, c4 = (idx & 7) * 4;
            av[i] = *(const float4*)(g_xn2 + (size_t)rows[r] * CC + k0 + c4);
        }
#pragma unroll
        for (int i = 0; i < 2; i++) {
            int idx = tid + i * 256, r = idx >> 4, c4 = (idx & 15) * 4;
            bv[i] = *(const float4*)(B + (size_t)(k0 + r) * FF + n0 + c4);
        }
        __syncthreads();
#pragma unroll
        for (int i = 0; i < 4; i++) {
            int idx = tid + i * 256, r = idx >> 3, c4 = (idx & 7) * 4;
            cvt4(&As[r][c4], av[i]);
        }
#pragma unroll
        for (int i = 0; i < 2; i++) {
            int idx = tid + i * 256, r = idx >> 4, c4 = (idx & 15) * 4;
            cvt4(&Bs[r][c4], bv[i]);
        }
        __syncthreads();
        MMA_CHUNK(As, Bs, acc, wm, wn, g, t4)
    }
#pragma unroll
    for (int mi = 0; mi < 2; mi++)
#pragma unroll
        for (int ni = 0; ni < 4; ni++) {
            int row = m0 + wm*32 + mi*16 + g;
            int col = n0 + wn*32 + ni*8 + 2*t4;
            float* c = acc[mi][ni];
            float2 bb = *(const float2*)(bias + col);
#pragma unroll
            for (int rr = 0; rr < 2; rr++) {
                int m = row + rr*8;
                if (m < Ne)
                    *(float2*)(g_h + (size_t)m * FF + col) =
                        make_float2(fmaxf(c[rr*2+0] + bb.x, 0.f),
                                    fmaxf(c[rr*2+1] + bb.y, 0.f));
            }
        }
}

// ---------------- MoE layer 2 (1xTF32): out[tok] += gate * (h@W2[e] + b2) ----------------
__global__ __launch_bounds__(256, 2) void moe2_tc(const float* __restrict__ W2, const float* __restrict__ b2,
                         float* __restrict__ out, int e) {
    int Ne = g_count[e];
    int m0 = blockIdx.y * 128;
    if (m0 >= Ne) return;
    int n0 = blockIdx.x * 64;
    const float* B = W2 + (size_t)e * FF * CC;
    const float* bias = b2 + (size_t)e * CC;
    __shared__ unsigned As[128][AP];
    __shared__ unsigned Bs[32][BP];
    int tid = threadIdx.x, lane = tid & 31, warp = tid >> 5;
    int wm = warp >> 1, wn = warp & 1, g = lane >> 2, t4 = lane & 3;
    float acc[2][4][4] = {};
    for (int k0 = 0; k0 < FF; k0 += 32) {
        float4 av[4], bv[2];
#pragma unroll
        for (int i = 0; i < 4; i++) {
            int idx = tid + i * 256, r = idx >> 3, c4 = (idx & 7) * 4;
            av[i] = *(const float4*)(g_h + (size_t)(m0 + r) * FF + k0 + c4);
        }
#pragma unroll
        for (int i = 0; i < 2; i++) {
            int idx = tid + i * 256, r = idx >> 4, c4 = (idx & 15) * 4;
            bv[i] = *(const float4*)(B + (size_t)(k0 + r) * CC + n0 + c4);
        }
        __syncthreads();
#pragma unroll
        for (int i = 0; i < 4; i++) {
            int idx = tid + i * 256, r = idx >> 3, c4 = (idx & 7) * 4;
            cvt4(&As[r][c4], av[i]);
        }
#pragma unroll
        for (int i = 0; i < 2; i++) {
            int idx = tid + i * 256, r = idx >> 4, c4 = (idx & 15) * 4;
            cvt4(&Bs[r][c4], bv[i]);
        }
        __syncthreads();
        MMA_CHUNK(As, Bs, acc, wm, wn, g, t4)
    }
#pragma unroll
    for (int mi = 0; mi < 2; mi++)
#pragma unroll
        for (int ni = 0; ni < 4; ni++) {
            int row = m0 + wm*32 + mi*16 + g;
            int col = n0 + wn*32 + ni*8 + 2*t4;
            float* c = acc[mi][ni];
            float2 bb = *(const float2*)(bias + col);
#pragma unroll
            for (int rr = 0; rr < 2; rr++) {
                int m = row + rr*8;
                if (m < Ne) {
                    int tok = g_list[e * TT + m];
                    float gv = g_lgate[e * TT + m];
                    float2* op = (float2*)(out + (size_t)tok * CC + col);
                    float2 o2 = *op;
                    o2.x += gv * (c[rr*2+0] + bb.x);
                    o2.y += gv * (c[rr*2+1] + bb.y);
                    *op = o2;
                }
            }
        }
}

// ---------------- host launcher ----------------
extern "C" void kernel_launch(void* const* d_in, const int* in_sizes, int n_in,
                              void* d_out, int out_size) {
    const float* x     = (const float*)d_in[0];
    const float* noise = (const float*)d_in[1];
    const float* ln1_g = (const float*)d_in[2];
    const float* ln1_b = (const float*)d_in[3];
    const float* ln2_g = (const float*)d_in[4];
    const float* ln2_b = (const float*)d_in[5];
    const float* Wq    = (const float*)d_in[6];
    const float* Wk    = (const float*)d_in[7];
    const float* Wv    = (const float*)d_in[8];
    const float* Wp    = (const float*)d_in[9];
    const float* bp    = (const float*)d_in[10];
    const float* Wr    = (const float*)d_in[11];
    const float* br    = (const float*)d_in[12];
    const float* Wn    = (const float*)d_in[13];
    const float* bn    = (const float*)d_in[14];
    const float* W1    = (const float*)d_in[15];
    const float* b1    = (const float*)d_in[16];
    const float* W2    = (const float*)d_in[17];
    const float* b2    = (const float*)d_in[18];
    float* out = (float*)d_out;

    // LN1
    ln_kernel<<<TT, 256>>>(x, ln1_g, ln1_b, 0);
    // QKV (3xTF32 — fp32-accurate, feeds the router-sensitive path)
    dim3 gq(TT / 128, HH);
    qkv_tc<<<gq, 256>>>(Wq, 0);
    qkv_tc<<<gq, 256>>>(Wk, 1);
    qkv_tc<<<gq, 256>>>(Wv, 2);
    // attention (fp32 SIMT)
    attn_kernel<<<dim3(TT / 64, HH), 256>>>();
    // proj + residual -> out (3xTF32)
    proj_tc<<<dim3(CC / 64, TT / 128), 256>>>(Wp, bp, x, out);
    // LN2 on x1
    ln_kernel<<<TT, 256>>>(out, ln2_g, ln2_b, 1);
    // router + lists (fp32)
    router_kernel<<<TT, 256>>>(Wr, br, Wn, bn, noise);
    build_lists<<<1, 256>>>();
    // MoE experts (1xTF32 — downstream of gating), sequential
    for (int e = 0; e < EE; e++) {
        moe1_tc<<<dim3(FF / 64, TT / 128), 256>>>(W1, b1, e);
        moe2_tc<<<dim3(CC / 64, TT / 128), 256>>>(W2, b2, out, e);
    }
}